// round 15
// baseline (speedup 1.0000x reference)
#include <cuda_runtime.h>
#include <cstdint>

#define Nn 32
#define Cc 256
#define Hh 32
#define Ww 32
#define HW (Hh*Ww)
#define NCHW (Nn*Cc*Hh*Ww)
#define NPIX (Nn*Hh*Ww)
#define NCHUNK 36
#define NUNITS (4*Nn*15)   // interior (oq, n, pair) units = 1920
#define NBUNITS (Nn*16)    // boundary groups (n, 8-pixel group) = 512

// ---------------- scratch (device globals; no allocation) ----------------
__device__ uint32_t           g_xbits[NPIX*8];        // channel-packed sign bits of current conv input
__device__ uint32_t           g_wchan[2][Cc*72];      // channel-packed weights [o][j=0..8][k=0..7]
__device__ unsigned long long g_wrT[2][NCHUNK*Cc];    // r-packed weights, transposed [chunk][o]
__device__ int8_t             g_y1b[NCHW];            // conv1 output, acc>>1 (acc provably even)
__device__ int8_t             g_y2b[NCHW];            // conv2 output, acc>>1 (pre-residual)
__device__ int                g_s1[Cc], g_q1[Cc];     // conv1 channel stats (exact int32)
__device__ double             g_S2[Cc], g_Q2[Cc];     // bn2 channel stats
__device__ unsigned long long g_vmask[9*NCHUNK];      // per boundary-class valid-bit mask per chunk
__device__ int                g_V[9*NCHUNK];          // valid counts
__device__ int                g_SV[9], g_NO[9];       // per-class: sum V, count of odd-V chunks
__device__ int                g_work[2];              // persistent-conv work counters
__device__ float              g_regbase;              // 3*G/1024

// ---------------- init: geometric tables + stat/counter reset + regularizer ----------------
__global__ void k_init() {
    int t = threadIdx.x;
    if (t < 9*NCHUNK) {
        int cls = t / NCHUNK, i = t % NCHUNK;
        int ht = cls / 3, wt = cls % 3;
        int r = 64*i, c = r/9, j = r - 9*c;
        unsigned long long m = 0;
        for (int b = 0; b < 64; b++) {
            int kh = j/3, kw = j - 3*kh;
            bool inval = (ht==0 && kh==0) || (ht==2 && kh==2) ||
                         (wt==0 && kw==0) || (wt==2 && kw==2);
            if (!inval) m |= 1ull << b;
            if (++j == 9) { j = 0; c++; }
        }
        g_vmask[t] = m;
        g_V[t] = __popcll(m);
    }
    if (t < Cc) { g_s1[t] = 0; g_q1[t] = 0; g_S2[t] = 0.0; g_Q2[t] = 0.0; }
    if (t < 2)  g_work[t] = 0;
    __syncthreads();
    if (t < 9) {
        int sv = 0, no = 0;
        for (int i = 0; i < NCHUNK; i++) { int V = g_V[t*NCHUNK + i]; sv += V; no += V & 1; }
        g_SV[t] = sv; g_NO[t] = no;
    }
    if (t == 0) {
        // reg = r1 + 2*r2 = 3 * sum_{chunks,pixels} parity / (H*W); parity is geometric
        long long G = 0;
        int npix[3] = {1, 30, 1};
        for (int cls = 0; cls < 9; cls++) {
            long long cnt = (long long)npix[cls/3] * npix[cls%3];
            for (int i = 0; i < NCHUNK; i++)
                G += cnt * (long long)(g_V[cls*NCHUNK + i] & 1);
        }
        g_regbase = 3.0f * (float)G / (float)HW;
    }
}

// ---------------- weight packing: both layouts, both convs, one kernel ----------------
__global__ void k_packw(const float* __restrict__ w1, const float* __restrict__ w2) {
    int o    = blockIdx.x & 255;
    int slot = blockIdx.x >> 8;
    const float* w = slot ? w2 : w1;
    int warp = threadIdx.x >> 5, lane = threadIdx.x & 31;

    // r-packed transposed: bit b of word [i][o] = sign(w[o, r=64i+b])
    for (int i = warp; i < NCHUNK; i += 8) {
        unsigned lo = __ballot_sync(0xffffffffu, w[o*2304 + 64*i + lane]      >= 0.f);
        unsigned hi = __ballot_sync(0xffffffffu, w[o*2304 + 64*i + 32 + lane] >= 0.f);
        if (lane == 0)
            g_wrT[slot][i*Cc + o] = (unsigned long long)lo | ((unsigned long long)hi << 32);
    }

    // channel-packed: word [o][j][c>>5], bit (c&31)
    int c = threadIdx.x;
    float v[9];
    #pragma unroll
    for (int j = 0; j < 9; j++) v[j] = w[o*2304 + c*9 + j];
    #pragma unroll
    for (int j = 0; j < 9; j++) {
        unsigned b = __ballot_sync(0xffffffffu, v[j] >= 0.f);
        if (lane == 0) g_wchan[slot][o*72 + j*8 + (c >> 5)] = b;
    }
}

// ---------------- input packing ----------------
__global__ void k_pack_x(const float* __restrict__ x) {
    int n = blockIdx.x >> 5, h = blockIdx.x & 31;
    int w = threadIdx.x & 31, k = threadIdx.x >> 5;
    const float* base = x + ((size_t)(n*Cc + k*32) * Hh + h) * Ww + w;
    uint32_t word = 0;
    #pragma unroll 8
    for (int cc = 0; cc < 32; cc++)
        if (base[(size_t)cc * HW] >= 0.f) word |= 1u << cc;
    g_xbits[((n*Hh + h)*Ww + w)*8 + k] = word;
}

// pack sign of bn1 (hardtanh preserves sign) with INLINE coef1: bit = (y*A1[c] + B1[c] >= 0)
__global__ void k_pack2(const float* __restrict__ gamma, const float* __restrict__ beta) {
    __shared__ float sA[Cc], sB[Cc];
    int t = threadIdx.x;
    {   // per-block coef computation — bit-identical to the old k_coef1
        double m   = (double)g_s1[t] / (double)(Nn*HW);
        double var = (double)g_q1[t] / (double)(Nn*HW) - m*m;
        float inv  = (float)(1.0 / sqrt(var + 1e-5));
        float A = gamma[t] * inv;
        sA[t] = A;
        sB[t] = beta[t] - (float)m * A;
    }
    __syncthreads();
    int n = blockIdx.x >> 5, h = blockIdx.x & 31;
    int w = t & 31, k = t >> 5;
    const int8_t* base = g_y1b + ((size_t)(n*Cc + k*32) * Hh + h) * Ww + w;
    uint32_t word = 0;
    #pragma unroll 8
    for (int cc = 0; cc < 32; cc++) {
        int c = k*32 + cc;
        float y = (float)(2 * (int)base[(size_t)cc * HW]);
        if (fmaf(y, sA[c], sB[c]) >= 0.f) word |= 1u << cc;
    }
    g_xbits[((n*Hh + h)*Ww + w)*8 + k] = word;
}

// ---------------- CSA helpers: single-LOP3 xor3 / majority ----------------
__device__ __forceinline__ uint32_t lop3_x3(uint32_t a, uint32_t b, uint32_t c) {
    uint32_t r;
    asm("lop3.b32 %0, %1, %2, %3, 0x96;" : "=r"(r) : "r"(a), "r"(b), "r"(c));
    return r;   // a ^ b ^ c
}
__device__ __forceinline__ uint32_t lop3_maj(uint32_t a, uint32_t b, uint32_t c) {
    uint32_t r;
    asm("lop3.b32 %0, %1, %2, %3, 0xE8;" : "=r"(r) : "r"(a), "r"(b), "r"(c));
    return r;   // majority(a,b,c)
}

// popcount of 8 XNOR-diff words via 4 full-adders: 4 POPC instead of 8.
// Sum popc(v0..v7) = popc(s3) + popc(v7) + 2*popc(s4) + 4*popc(c4)   (exact)
__device__ __forceinline__ int tap_count(uint4 xa, uint4 xb, uint4 wa, uint4 wb) {
    uint32_t v0 = xa.x ^ wa.x, v1 = xa.y ^ wa.y, v2 = xa.z ^ wa.z, v3 = xa.w ^ wa.w;
    uint32_t v4 = xb.x ^ wb.x, v5 = xb.y ^ wb.y, v6 = xb.z ^ wb.z, v7 = xb.w ^ wb.w;
    uint32_t sA = lop3_x3(v0, v1, v2), cA = lop3_maj(v0, v1, v2);
    uint32_t sB = lop3_x3(v3, v4, v5), cB = lop3_maj(v3, v4, v5);
    uint32_t s3 = lop3_x3(sA, sB, v6), c3 = lop3_maj(sA, sB, v6);
    uint32_t s4 = lop3_x3(cA, cB, c3), c4 = lop3_maj(cA, cB, c3);
    return __popc(s3) + __popc(v7) + 2*__popc(s4) + 4*__popc(c4);
}

// boundary per-chunk step: psum_q folded via packed (sumP | ccnt<<16); exact banker's rounding
__device__ __forceinline__ void bstep(uint32_t& acc, unsigned long long s, unsigned long long w64,
                                      unsigned long long m, uint32_t v2, uint32_t od) {
    unsigned long long X = (s ^ w64) & m;
    uint32_t P = __popcll(X);
    uint32_t tt = (P ^ v2) & od;
    acc += P + (tt << 16);
}

// ---------------- unified conv: persistent work-stealing over interior units + boundary groups ----
// units [0, NUNITS): interior (oq, n, pair); units [NUNITS, NUNITS+NBUNITS): boundary (n, group)
template<int MODE>   // 1: write y1b + int stats; 2: write y2b + float stats on z=acc+res
__global__ void __launch_bounds__(256, 2) k_conv_all(const float* __restrict__ x0res, int slot) {
    __shared__ __align__(16) uint32_t sx[4][Ww][8];      // 4 KB   (interior halo rows)
    __shared__ __align__(16) uint32_t sw[64*72];         // 18 KB  (interior: current oq weights)
    __shared__ unsigned long long s_vm[9*NCHUNK];        // 2.6 KB (boundary tables)
    __shared__ int                s_V[9*NCHUNK];         // 1.3 KB
    __shared__ unsigned long long sxr[8][NCHUNK];        // 2.3 KB (boundary pixel words)
    __shared__ int                s_hw[8];
    __shared__ int s_u;
    int t = threadIdx.x;
    int w = t & 31, warp = t >> 5, lane = w;
    int wl = (w > 0) ? w-1 : 0;
    int wr = (w < 31) ? w+1 : 31;
    const int wcol[3] = {wl, w, wr};
    bool valid = (w >= 1 && w <= 30);
    int ob = warp*8;
    int cur_oq = -1;

    for (int i = t; i < 9*NCHUNK; i += 256) { s_vm[i] = g_vmask[i]; s_V[i] = g_V[i]; }

    for (;;) {
        __syncthreads();            // all threads done with prior sx/sw/sxr
        if (t == 0) s_u = atomicAdd(&g_work[MODE-1], 1);
        __syncthreads();            // publish s_u
        int u = s_u;
        if (u >= NUNITS + NBUNITS) break;

        if (u < NUNITS) {
            // ---------------- interior unit ----------------
            int oq   = u / (NUNITS/4);
            int rem  = u - oq*(NUNITS/4);
            int n    = rem / 15, pair = rem - n*15;

            if (oq != cur_oq) {
                const uint4* gsrc = (const uint4*)(g_wchan[slot] + oq*64*72);
                #pragma unroll
                for (int i = 0; i < 1152/256; i++) ((uint4*)sw)[t + i*256] = gsrc[t + i*256];
                if (t < 128) ((uint4*)sw)[1024 + t] = gsrc[1024 + t];
                cur_oq = oq;
            }
            int h0 = 1 + 2*pair;
            ((uint4*)sx)[t] = ((const uint4*)(g_xbits + (size_t)(n*Hh + (h0-1)) * Ww * 8))[t];
            __syncthreads();

            size_t base0 = (((size_t)n*Cc*Hh) + h0) * Ww + w;

            int s01[8];
            #pragma unroll
            for (int oo = 0; oo < 8; oo++) s01[oo] = 0;

            #pragma unroll
            for (int j = 0; j < 9; j++) {
                int rr = j / 3;
                int wc = wcol[j % 3];
                const uint32_t* xp0 = &sx[rr][wc][0];
                uint4 xa = *(const uint4*)xp0;
                uint4 xb = *(const uint4*)(xp0 + 4);
                const uint32_t* xp1 = &sx[rr+1][wc][0];
                uint4 ya = *(const uint4*)xp1;
                uint4 yb = *(const uint4*)(xp1 + 4);
                #pragma unroll
                for (int oo = 0; oo < 8; oo++) {
                    const uint4* wp = (const uint4*)(&sw[(ob + oo)*72 + j*8]);
                    uint4 wa = wp[0];
                    uint4 wb = wp[1];
                    int t0 = tap_count(xa, xb, wa, wb);
                    int t1 = tap_count(ya, yb, wa, wb);
                    s01[oo] += t0 + (t1 << 16);
                }
            }

            #pragma unroll
            for (int oo = 0; oo < 8; oo++) {
                int o = cur_oq*64 + ob + oo;
                int s0 = s01[oo] & 0xFFFF;
                int s1 = s01[oo] >> 16;
                int a0 = min(max(2304 - 2*s0, -254), 254);
                int a1 = min(max(2304 - 2*s1, -254), 254);
                size_t idx = base0 + (size_t)o * HW;
                if (MODE == 1) {
                    if (valid) { g_y1b[idx] = (int8_t)(a0 >> 1); g_y1b[idx + Ww] = (int8_t)(a1 >> 1); }
                    int vs = valid ? (a0 + a1) : 0;
                    int vq = valid ? (a0*a0 + a1*a1) : 0;
                    vs = __reduce_add_sync(0xffffffffu, vs);
                    vq = __reduce_add_sync(0xffffffffu, vq);
                    if (w == 0) { atomicAdd(&g_s1[o], vs); atomicAdd(&g_q1[o], vq); }
                } else {
                    float z0 = 0.f, z1 = 0.f;
                    if (valid) {
                        z0 = (float)a0 + x0res[idx];
                        z1 = (float)a1 + x0res[idx + Ww];
                        g_y2b[idx] = (int8_t)(a0 >> 1); g_y2b[idx + Ww] = (int8_t)(a1 >> 1);
                    }
                    float fs = z0 + z1, fq = z0*z0 + z1*z1;
                    #pragma unroll
                    for (int d = 16; d; d >>= 1) {
                        fs += __shfl_xor_sync(0xffffffffu, fs, d);
                        fq += __shfl_xor_sync(0xffffffffu, fq, d);
                    }
                    if (w == 0) { atomicAdd(&g_S2[o], (double)fs); atomicAdd(&g_Q2[o], (double)fq); }
                }
            }
        } else {
            // ---------------- boundary group (8 pixels) ----------------
            int ub = u - NUNITS;
            int g = ub & 15, n = ub >> 4;

            int p = g*8 + warp;
            if (p < 124) {
                int h, ww_;
                if      (p < 32) { h = 0;      ww_ = p; }
                else if (p < 64) { h = 31;     ww_ = p - 32; }
                else if (p < 94) { ww_ = 0;    h = p - 63; }
                else             { ww_ = 31;   h = p - 93; }
                int ht = (h == 0) ? 0 : ((h == 31) ? 2 : 1);
                int wt = (ww_ == 0) ? 0 : ((ww_ == 31) ? 2 : 1);
                if (lane == 0) s_hw[warp] = (h << 16) | (ww_ << 8) | (ht*3 + wt);
                for (int i = 0; i < NCHUNK; i++) {
                    int r0 = 64*i + lane;
                    int c0 = r0 / 9, j0 = r0 - 9*c0;
                    int kh0 = j0 / 3, kw0 = j0 - 3*kh0;
                    int hh0 = min(max(h + kh0 - 1, 0), 31), ww0 = min(max(ww_ + kw0 - 1, 0), 31);
                    unsigned lo = __ballot_sync(0xffffffffu,
                        (g_xbits[((n*Hh + hh0)*Ww + ww0)*8 + (c0 >> 5)] >> (c0 & 31)) & 1u);
                    int r1 = r0 + 32;
                    int c1 = r1 / 9, j1 = r1 - 9*c1;
                    int kh1 = j1 / 3, kw1 = j1 - 3*kh1;
                    int hh1 = min(max(h + kh1 - 1, 0), 31), ww1 = min(max(ww_ + kw1 - 1, 0), 31);
                    unsigned hi = __ballot_sync(0xffffffffu,
                        (g_xbits[((n*Hh + hh1)*Ww + ww1)*8 + (c1 >> 5)] >> (c1 & 31)) & 1u);
                    if (lane == 0)
                        sxr[warp][i] = (unsigned long long)lo | ((unsigned long long)hi << 32);
                }
            }
            __syncthreads();

            int o = t;
            int np = min(124 - g*8, 8);
            int cb[8];
            #pragma unroll
            for (int k = 0; k < 8; k++) cb[k] = (k < np) ? (s_hw[k] & 255) * NCHUNK : 0;

            uint32_t acc[8];
            #pragma unroll
            for (int k = 0; k < 8; k++) acc[k] = 0;

            const unsigned long long* wrp = g_wrT[slot];
            for (int i = 0; i < NCHUNK; i++) {
                unsigned long long w64 = wrp[i*Cc + o];
                #pragma unroll
                for (int k = 0; k < 8; k++) {
                    if (k < np) {
                        unsigned long long m = s_vm[cb[k] + i];
                        int V = s_V[cb[k] + i];
                        bstep(acc[k], sxr[k][i], w64, m, (uint32_t)((V >> 1) & 1), (uint32_t)(V & 1));
                    }
                }
            }

            int    sumS = 0, sumQ = 0;
            double dz = 0.0, dq = 0.0;
            #pragma unroll
            for (int k = 0; k < 8; k++) {
                if (k < np) {
                    int info = s_hw[k];
                    int h = info >> 16, ww_ = (info >> 8) & 255, ck = info & 255;
                    int sumP = (int)(acc[k] & 0xFFFF);
                    int ccnt = (int)(acc[k] >> 16);
                    int a = g_SV[ck] - 2*sumP + 2*ccnt - g_NO[ck];
                    a = min(max(a, -254), 254);
                    size_t idx = ((size_t)(n*Cc + o) * Hh + h) * Ww + ww_;
                    if (MODE == 1) {
                        g_y1b[idx] = (int8_t)(a >> 1);
                        sumS += a; sumQ += a*a;
                    } else {
                        float z = (float)a + x0res[idx];
                        g_y2b[idx] = (int8_t)(a >> 1);
                        dz += (double)z; dq += (double)(z*z);
                    }
                }
            }
            if (MODE == 1) { atomicAdd(&g_s1[o], sumS); atomicAdd(&g_q1[o], sumQ); }
            else           { atomicAdd(&g_S2[o], dz);   atomicAdd(&g_Q2[o], dq); }
        }
    }
}

// ---------------- finalize: INLINE coef2, z = 2*y2b + residual, bn2 + hardtanh, reg scalar -------
__global__ void k_final(float* __restrict__ out, const float* __restrict__ reg0,
                        const float* __restrict__ x0,
                        const float* __restrict__ gamma, const float* __restrict__ beta,
                        int out_size) {
    __shared__ float sAB[2];
    int t = threadIdx.x;
    int o = blockIdx.x & 255;           // each block covers 1024 consecutive floats = one (n,o) plane
    if (t == 0) {                       // bit-identical to the old k_coef2
        double m   = g_S2[o] / (double)(Nn*HW);
        double var = g_Q2[o] / (double)(Nn*HW) - m*m;
        float inv  = (float)(1.0 / sqrt(var + 1e-5));
        float A = gamma[o] * inv;
        sAB[0] = A;
        sAB[1] = beta[o] - (float)m * A;
    }
    __syncthreads();
    float A = sAB[0], B = sAB[1];
    size_t v = (size_t)blockIdx.x * 256 + t;
    size_t idx = v * 4;
    char4 a = *(const char4*)(g_y2b + idx);
    float4 x = *(const float4*)(x0 + idx);
    float4 r;
    // z = (float)acc + x0 — bitwise identical to the value used in fused stats
    r.x = fminf(fmaxf(fmaf((float)(2*(int)a.x) + x.x, A, B), -1.f), 1.f);
    r.y = fminf(fmaxf(fmaf((float)(2*(int)a.y) + x.y, A, B), -1.f), 1.f);
    r.z = fminf(fmaxf(fmaf((float)(2*(int)a.z) + x.z, A, B), -1.f), 1.f);
    r.w = fminf(fmaxf(fmaf((float)(2*(int)a.w) + x.w, A, B), -1.f), 1.f);
    *(float4*)(out + idx) = r;
    if (v == 0) out[out_size - 1] = reg0[0] + g_regbase;
}

// ---------------- launch ----------------
extern "C" void kernel_launch(void* const* d_in, const int* in_sizes, int n_in,
                              void* d_out, int out_size) {
    const float* x0   = (const float*)d_in[0];
    const float* reg0 = (const float*)d_in[1];
    const float* w1   = (const float*)d_in[2];
    const float* g1   = (const float*)d_in[3];
    const float* b1   = (const float*)d_in[4];
    const float* w2   = (const float*)d_in[5];
    const float* g2   = (const float*)d_in[6];
    const float* b2   = (const float*)d_in[7];
    float* out = (float*)d_out;

    k_init<<<1, 512>>>();                       // 0
    k_packw<<<512, 256>>>(w1, w2);              // 1
    k_pack_x<<<Nn*Hh, 256>>>(x0);               // 2
    k_conv_all<1><<<296, 256>>>(nullptr, 0);    // 3  interior + boundary, work queue 0
    k_pack2<<<Nn*Hh, 256>>>(g1, b1);            // 4  inline coef1
    k_conv_all<2><<<296, 256>>>(x0, 1);         // 5  interior + boundary, work queue 1
    k_final<<<NCHW/1024, 256>>>(out, reg0, x0, g2, b2, out_size);  // 6  inline coef2
}

// round 16
// speedup vs baseline: 1.6385x; 1.6385x over previous
#include <cuda_runtime.h>
#include <cstdint>

#define Nn 32
#define Cc 256
#define Hh 32
#define Ww 32
#define HW (Hh*Ww)
#define NCHW (Nn*Cc*Hh*Ww)
#define NPIX (Nn*Hh*Ww)
#define NCHUNK 36
#define NUNITS (4*Nn*15)   // (oq, n, pair) work units = 1920

// ---------------- scratch (device globals; no allocation) ----------------
__device__ uint32_t           g_xbits[NPIX*8];        // channel-packed sign bits of current conv input
__device__ uint32_t           g_wchan[2][Cc*72];      // channel-packed weights [o][j=0..8][k=0..7]
__device__ unsigned long long g_wrT[2][NCHUNK*Cc];    // r-packed weights, transposed [chunk][o]
__device__ int8_t             g_y1b[NCHW];            // conv1 output, acc>>1 (acc provably even)
__device__ int8_t             g_y2b[NCHW];            // conv2 output, acc>>1 (pre-residual)
__device__ int                g_s1[Cc], g_q1[Cc];     // conv1 channel stats (exact int32)
__device__ double             g_S2[Cc], g_Q2[Cc];     // bn2 channel stats
__device__ unsigned long long g_vmask[9*NCHUNK];      // per boundary-class valid-bit mask per chunk
__device__ int                g_V[9*NCHUNK];          // valid counts
__device__ int                g_SV[9], g_NO[9];       // per-class: sum V, count of odd-V chunks
__device__ int                g_work[2];              // persistent-conv work counters
__device__ float              g_regbase;              // 3*G/1024

// ---------------- init: geometric tables + stat/counter reset + regularizer ----------------
__global__ void k_init() {
    int t = threadIdx.x;
    if (t < 9*NCHUNK) {
        int cls = t / NCHUNK, i = t % NCHUNK;
        int ht = cls / 3, wt = cls % 3;
        int r = 64*i, c = r/9, j = r - 9*c;
        unsigned long long m = 0;
        for (int b = 0; b < 64; b++) {
            int kh = j/3, kw = j - 3*kh;
            bool inval = (ht==0 && kh==0) || (ht==2 && kh==2) ||
                         (wt==0 && kw==0) || (wt==2 && kw==2);
            if (!inval) m |= 1ull << b;
            if (++j == 9) { j = 0; c++; }
        }
        g_vmask[t] = m;
        g_V[t] = __popcll(m);
    }
    if (t < Cc) { g_s1[t] = 0; g_q1[t] = 0; g_S2[t] = 0.0; g_Q2[t] = 0.0; }
    if (t < 2)  g_work[t] = 0;
    __syncthreads();
    if (t < 9) {
        int sv = 0, no = 0;
        for (int i = 0; i < NCHUNK; i++) { int V = g_V[t*NCHUNK + i]; sv += V; no += V & 1; }
        g_SV[t] = sv; g_NO[t] = no;
    }
    if (t == 0) {
        // reg = r1 + 2*r2 = 3 * sum_{chunks,pixels} parity / (H*W); parity is geometric
        long long G = 0;
        int npix[3] = {1, 30, 1};
        for (int cls = 0; cls < 9; cls++) {
            long long cnt = (long long)npix[cls/3] * npix[cls%3];
            for (int i = 0; i < NCHUNK; i++)
                G += cnt * (long long)(g_V[cls*NCHUNK + i] & 1);
        }
        g_regbase = 3.0f * (float)G / (float)HW;
    }
}

// ---------------- weight packing: both layouts, both convs, one kernel ----------------
__global__ void k_packw(const float* __restrict__ w1, const float* __restrict__ w2) {
    int o    = blockIdx.x & 255;
    int slot = blockIdx.x >> 8;
    const float* w = slot ? w2 : w1;
    int warp = threadIdx.x >> 5, lane = threadIdx.x & 31;

    // r-packed transposed: bit b of word [i][o] = sign(w[o, r=64i+b])
    for (int i = warp; i < NCHUNK; i += 8) {
        unsigned lo = __ballot_sync(0xffffffffu, w[o*2304 + 64*i + lane]      >= 0.f);
        unsigned hi = __ballot_sync(0xffffffffu, w[o*2304 + 64*i + 32 + lane] >= 0.f);
        if (lane == 0)
            g_wrT[slot][i*Cc + o] = (unsigned long long)lo | ((unsigned long long)hi << 32);
    }

    // channel-packed: word [o][j][c>>5], bit (c&31)
    int c = threadIdx.x;
    float v[9];
    #pragma unroll
    for (int j = 0; j < 9; j++) v[j] = w[o*2304 + c*9 + j];
    #pragma unroll
    for (int j = 0; j < 9; j++) {
        unsigned b = __ballot_sync(0xffffffffu, v[j] >= 0.f);
        if (lane == 0) g_wchan[slot][o*72 + j*8 + (c >> 5)] = b;
    }
}

// ---------------- input packing ----------------
__global__ void k_pack_x(const float* __restrict__ x) {
    int n = blockIdx.x >> 5, h = blockIdx.x & 31;
    int w = threadIdx.x & 31, k = threadIdx.x >> 5;
    const float* base = x + ((size_t)(n*Cc + k*32) * Hh + h) * Ww + w;
    uint32_t word = 0;
    #pragma unroll 8
    for (int cc = 0; cc < 32; cc++)
        if (base[(size_t)cc * HW] >= 0.f) word |= 1u << cc;
    g_xbits[((n*Hh + h)*Ww + w)*8 + k] = word;
}

// pack sign of bn1 (hardtanh preserves sign) with INLINE coef1: bit = (y*A1[c] + B1[c] >= 0)
__global__ void k_pack2(const float* __restrict__ gamma, const float* __restrict__ beta) {
    __shared__ float sA[Cc], sB[Cc];
    int t = threadIdx.x;
    {   // per-block coef computation — bit-identical to the old k_coef1
        double m   = (double)g_s1[t] / (double)(Nn*HW);
        double var = (double)g_q1[t] / (double)(Nn*HW) - m*m;
        float inv  = (float)(1.0 / sqrt(var + 1e-5));
        float A = gamma[t] * inv;
        sA[t] = A;
        sB[t] = beta[t] - (float)m * A;
    }
    __syncthreads();
    int n = blockIdx.x >> 5, h = blockIdx.x & 31;
    int w = t & 31, k = t >> 5;
    const int8_t* base = g_y1b + ((size_t)(n*Cc + k*32) * Hh + h) * Ww + w;
    uint32_t word = 0;
    #pragma unroll 8
    for (int cc = 0; cc < 32; cc++) {
        int c = k*32 + cc;
        float y = (float)(2 * (int)base[(size_t)cc * HW]);
        if (fmaf(y, sA[c], sB[c]) >= 0.f) word |= 1u << cc;
    }
    g_xbits[((n*Hh + h)*Ww + w)*8 + k] = word;
}

// ---------------- CSA helpers: single-LOP3 xor3 / majority ----------------
__device__ __forceinline__ uint32_t lop3_x3(uint32_t a, uint32_t b, uint32_t c) {
    uint32_t r;
    asm("lop3.b32 %0, %1, %2, %3, 0x96;" : "=r"(r) : "r"(a), "r"(b), "r"(c));
    return r;   // a ^ b ^ c
}
__device__ __forceinline__ uint32_t lop3_maj(uint32_t a, uint32_t b, uint32_t c) {
    uint32_t r;
    asm("lop3.b32 %0, %1, %2, %3, 0xE8;" : "=r"(r) : "r"(a), "r"(b), "r"(c));
    return r;   // majority(a,b,c)
}

// popcount of 8 XNOR-diff words via 4 full-adders: 4 POPC instead of 8.
// Sum popc(v0..v7) = popc(s3) + popc(v7) + 2*popc(s4) + 4*popc(c4)   (exact)
__device__ __forceinline__ int tap_count(uint4 xa, uint4 xb, uint4 wa, uint4 wb) {
    uint32_t v0 = xa.x ^ wa.x, v1 = xa.y ^ wa.y, v2 = xa.z ^ wa.z, v3 = xa.w ^ wa.w;
    uint32_t v4 = xb.x ^ wb.x, v5 = xb.y ^ wb.y, v6 = xb.z ^ wb.z, v7 = xb.w ^ wb.w;
    uint32_t sA = lop3_x3(v0, v1, v2), cA = lop3_maj(v0, v1, v2);
    uint32_t sB = lop3_x3(v3, v4, v5), cB = lop3_maj(v3, v4, v5);
    uint32_t s3 = lop3_x3(sA, sB, v6), c3 = lop3_maj(sA, sB, v6);
    uint32_t s4 = lop3_x3(cA, cB, c3), c4 = lop3_maj(cA, cB, c3);
    return __popc(s3) + __popc(v7) + 2*__popc(s4) + 4*__popc(c4);
}

// ---------------- interior conv: persistent blocks + work-stealing over (oq, n, pair) ----------------
// grid = 296 = 2 blocks/SM uniform; units oq-major so smem weights are reused across units.
// quantization is an exact no-op for interior pixels (psum always even, |psum|<=64)
template<int MODE>   // 1: write y1b + int stats; 2: write y2b + float stats on z=acc+res
__global__ void __launch_bounds__(256, 2) k_conv_int(const float* __restrict__ x0res, int slot) {
    __shared__ __align__(16) uint32_t sx[4][Ww][8];      // 4 KB
    __shared__ __align__(16) uint32_t sw[64*72];         // 18 KB: current oq's 64-o weights
    __shared__ int s_u;
    int t = threadIdx.x;
    int w = t & 31, warp = t >> 5;
    int wl = (w > 0) ? w-1 : 0;
    int wr = (w < 31) ? w+1 : 31;
    const int wcol[3] = {wl, w, wr};
    bool valid = (w >= 1 && w <= 30);
    int ob = warp*8;   // this warp's 8 o's within the oq quarter
    int cur_oq = -1;

    for (;;) {
        if (t == 0) s_u = atomicAdd(&g_work[MODE-1], 1);
        __syncthreads();            // publish s_u; all threads done with prior sx/sw
        int u = s_u;
        if (u >= NUNITS) break;
        int oq   = u / (NUNITS/4);
        int rem  = u - oq*(NUNITS/4);
        int n    = rem / 15, pair = rem - n*15;

        if (oq != cur_oq) {         // (re)load weights for this quarter: 1152 uint4
            const uint4* gsrc = (const uint4*)(g_wchan[slot] + oq*64*72);
            #pragma unroll
            for (int i = 0; i < 1152/256; i++) ((uint4*)sw)[t + i*256] = gsrc[t + i*256];
            if (t < 128) ((uint4*)sw)[1024 + t] = gsrc[1024 + t];
            cur_oq = oq;
        }
        int h0 = 1 + 2*pair;        // rows h0, h0+1; halo rows h0-1..h0+2
        ((uint4*)sx)[t] = ((const uint4*)(g_xbits + (size_t)(n*Hh + (h0-1)) * Ww * 8))[t];
        __syncthreads();

        size_t base0 = (((size_t)n*Cc*Hh) + h0) * Ww + w;   // + o*HW

        // packed accumulators: low 16 = row0 popc-sum, high 16 = row1 (each <= 2304, no carry)
        int s01[8];
        #pragma unroll
        for (int oo = 0; oo < 8; oo++) s01[oo] = 0;

        #pragma unroll
        for (int j = 0; j < 9; j++) {
            int rr = j / 3;
            int wc = wcol[j % 3];
            const uint32_t* xp0 = &sx[rr][wc][0];
            uint4 xa = *(const uint4*)xp0;
            uint4 xb = *(const uint4*)(xp0 + 4);
            const uint32_t* xp1 = &sx[rr+1][wc][0];
            uint4 ya = *(const uint4*)xp1;
            uint4 yb = *(const uint4*)(xp1 + 4);
            #pragma unroll
            for (int oo = 0; oo < 8; oo++) {
                const uint4* wp = (const uint4*)(&sw[(ob + oo)*72 + j*8]);
                uint4 wa = wp[0];
                uint4 wb = wp[1];
                int t0 = tap_count(xa, xb, wa, wb);
                int t1 = tap_count(ya, yb, wa, wb);
                s01[oo] += t0 + (t1 << 16);
            }
        }

        #pragma unroll
        for (int oo = 0; oo < 8; oo++) {
            int o = cur_oq*64 + ob + oo;
            int s0 = s01[oo] & 0xFFFF;
            int s1 = s01[oo] >> 16;
            int a0 = min(max(2304 - 2*s0, -254), 254);
            int a1 = min(max(2304 - 2*s1, -254), 254);
            size_t idx = base0 + (size_t)o * HW;
            if (MODE == 1) {
                if (valid) { g_y1b[idx] = (int8_t)(a0 >> 1); g_y1b[idx + Ww] = (int8_t)(a1 >> 1); }
                int vs = valid ? (a0 + a1) : 0;
                int vq = valid ? (a0*a0 + a1*a1) : 0;
                vs = __reduce_add_sync(0xffffffffu, vs);
                vq = __reduce_add_sync(0xffffffffu, vq);
                if (w == 0) { atomicAdd(&g_s1[o], vs); atomicAdd(&g_q1[o], vq); }
            } else {
                float z0 = 0.f, z1 = 0.f;
                if (valid) {
                    z0 = (float)a0 + x0res[idx];
                    z1 = (float)a1 + x0res[idx + Ww];
                    g_y2b[idx] = (int8_t)(a0 >> 1); g_y2b[idx + Ww] = (int8_t)(a1 >> 1);
                }
                float fs = z0 + z1, fq = z0*z0 + z1*z1;
                #pragma unroll
                for (int d = 16; d; d >>= 1) {
                    fs += __shfl_xor_sync(0xffffffffu, fs, d);
                    fq += __shfl_xor_sync(0xffffffffu, fq, d);
                }
                if (w == 0) { atomicAdd(&g_S2[o], (double)fs); atomicAdd(&g_Q2[o], (double)fq); }
            }
        }
    }
}

// ---------------- boundary conv v3: 8 pixels/block, shared wrT loads, smem tables ----------------
// per odd-V chunk: corr = 2*((P&1)^((V>>1)&1)) - 1 (banker's rounding, exact — verified r7)
// acc_final = SV - 2*sumP + 2*ccnt - NO
__device__ __forceinline__ void bstep(uint32_t& acc, unsigned long long s, unsigned long long w64,
                                      unsigned long long m, uint32_t v2, uint32_t od) {
    unsigned long long X = (s ^ w64) & m;
    uint32_t P = __popcll(X);
    uint32_t tt = (P ^ v2) & od;
    acc += P + (tt << 16);
}

template<int MODE>
__global__ void __launch_bounds__(256, 4) k_conv_bnd(const float* __restrict__ x0res, int slot) {
    int g = blockIdx.x & 15, n = blockIdx.x >> 4;   // 16 groups of 8 boundary pixels
    __shared__ unsigned long long s_vm[9*NCHUNK];
    __shared__ int                s_V[9*NCHUNK];
    __shared__ unsigned long long sxr[8][NCHUNK];
    __shared__ int                s_hw[8];          // (h<<16)|(w<<8)|cls
    int t = threadIdx.x, warp = t >> 5, lane = t & 31;

    for (int i = t; i < 9*NCHUNK; i += 256) { s_vm[i] = g_vmask[i]; s_V[i] = g_V[i]; }

    // warp k builds pixel p = g*8+k: 36 r-ordered chunk words via ballot
    int p = g*8 + warp;
    if (p < 124) {
        int h, w;
        if      (p < 32) { h = 0;      w = p; }
        else if (p < 64) { h = 31;     w = p - 32; }
        else if (p < 94) { w = 0;      h = p - 63; }
        else             { w = 31;     h = p - 93; }
        int ht = (h == 0) ? 0 : ((h == 31) ? 2 : 1);
        int wt = (w == 0) ? 0 : ((w == 31) ? 2 : 1);
        if (lane == 0) s_hw[warp] = (h << 16) | (w << 8) | (ht*3 + wt);
        for (int i = 0; i < NCHUNK; i++) {
            int r0 = 64*i + lane;
            int c0 = r0 / 9, j0 = r0 - 9*c0;
            int kh0 = j0 / 3, kw0 = j0 - 3*kh0;
            int hh0 = min(max(h + kh0 - 1, 0), 31), ww0 = min(max(w + kw0 - 1, 0), 31);
            unsigned lo = __ballot_sync(0xffffffffu,
                (g_xbits[((n*Hh + hh0)*Ww + ww0)*8 + (c0 >> 5)] >> (c0 & 31)) & 1u);
            int r1 = r0 + 32;
            int c1 = r1 / 9, j1 = r1 - 9*c1;
            int kh1 = j1 / 3, kw1 = j1 - 3*kh1;
            int hh1 = min(max(h + kh1 - 1, 0), 31), ww1 = min(max(w + kw1 - 1, 0), 31);
            unsigned hi = __ballot_sync(0xffffffffu,
                (g_xbits[((n*Hh + hh1)*Ww + ww1)*8 + (c1 >> 5)] >> (c1 & 31)) & 1u);
            if (lane == 0)
                sxr[warp][i] = (unsigned long long)lo | ((unsigned long long)hi << 32);
        }
    }
    __syncthreads();

    int o = t;                        // each thread owns one output channel for all 8 pixels
    int np = min(124 - g*8, 8);       // 8, except last group (4)
    int cb[8];                        // per-pixel class table base
    #pragma unroll
    for (int k = 0; k < 8; k++) cb[k] = (k < np) ? (s_hw[k] & 255) * NCHUNK : 0;

    uint32_t acc[8];
    #pragma unroll
    for (int k = 0; k < 8; k++) acc[k] = 0;

    const unsigned long long* wr = g_wrT[slot];
    for (int i = 0; i < NCHUNK; i++) {
        unsigned long long w64 = wr[i*Cc + o];    // one LDG serves 8 pixels
        #pragma unroll
        for (int k = 0; k < 8; k++) {
            if (k < np) {
                unsigned long long m = s_vm[cb[k] + i];
                int V = s_V[cb[k] + i];
                bstep(acc[k], sxr[k][i], w64, m, (uint32_t)((V >> 1) & 1), (uint32_t)(V & 1));
            }
        }
    }

    int    sumS = 0, sumQ = 0;
    double dz = 0.0, dq = 0.0;
    #pragma unroll
    for (int k = 0; k < 8; k++) {
        if (k < np) {
            int info = s_hw[k];
            int h = info >> 16, w = (info >> 8) & 255, ck = info & 255;
            int sumP = (int)(acc[k] & 0xFFFF);
            int ccnt = (int)(acc[k] >> 16);
            int a = g_SV[ck] - 2*sumP + 2*ccnt - g_NO[ck];
            a = min(max(a, -254), 254);
            size_t idx = ((size_t)(n*Cc + o) * Hh + h) * Ww + w;
            if (MODE == 1) {
                g_y1b[idx] = (int8_t)(a >> 1);
                sumS += a; sumQ += a*a;
            } else {
                float z = (float)a + x0res[idx];
                g_y2b[idx] = (int8_t)(a >> 1);
                dz += (double)z; dq += (double)(z*z);
            }
        }
    }
    if (MODE == 1) { atomicAdd(&g_s1[o], sumS); atomicAdd(&g_q1[o], sumQ); }
    else           { atomicAdd(&g_S2[o], dz);   atomicAdd(&g_Q2[o], dq); }
}

// ---------------- finalize: INLINE coef2, z = 2*y2b + residual, bn2 + hardtanh, reg scalar -------
__global__ void k_final(float* __restrict__ out, const float* __restrict__ reg0,
                        const float* __restrict__ x0,
                        const float* __restrict__ gamma, const float* __restrict__ beta,
                        int out_size) {
    __shared__ float sAB[2];
    int t = threadIdx.x;
    int o = blockIdx.x & 255;           // each block covers 1024 consecutive floats = one (n,o) plane
    if (t == 0) {                       // bit-identical to the old k_coef2
        double m   = g_S2[o] / (double)(Nn*HW);
        double var = g_Q2[o] / (double)(Nn*HW) - m*m;
        float inv  = (float)(1.0 / sqrt(var + 1e-5));
        float A = gamma[o] * inv;
        sAB[0] = A;
        sAB[1] = beta[o] - (float)m * A;
    }
    __syncthreads();
    float A = sAB[0], B = sAB[1];
    size_t v = (size_t)blockIdx.x * 256 + t;
    size_t idx = v * 4;
    char4 a = *(const char4*)(g_y2b + idx);
    float4 x = *(const float4*)(x0 + idx);
    float4 r;
    // z = (float)acc + x0 — bitwise identical to the value used in fused stats
    r.x = fminf(fmaxf(fmaf((float)(2*(int)a.x) + x.x, A, B), -1.f), 1.f);
    r.y = fminf(fmaxf(fmaf((float)(2*(int)a.y) + x.y, A, B), -1.f), 1.f);
    r.z = fminf(fmaxf(fmaf((float)(2*(int)a.z) + x.z, A, B), -1.f), 1.f);
    r.w = fminf(fmaxf(fmaf((float)(2*(int)a.w) + x.w, A, B), -1.f), 1.f);
    *(float4*)(out + idx) = r;
    if (v == 0) out[out_size - 1] = reg0[0] + g_regbase;
}

// ---------------- launch ----------------
extern "C" void kernel_launch(void* const* d_in, const int* in_sizes, int n_in,
                              void* d_out, int out_size) {
    const float* x0   = (const float*)d_in[0];
    const float* reg0 = (const float*)d_in[1];
    const float* w1   = (const float*)d_in[2];
    const float* g1   = (const float*)d_in[3];
    const float* b1   = (const float*)d_in[4];
    const float* w2   = (const float*)d_in[5];
    const float* g2   = (const float*)d_in[6];
    const float* b2   = (const float*)d_in[7];
    float* out = (float*)d_out;

    k_init<<<1, 512>>>();                       // 0
    k_packw<<<512, 256>>>(w1, w2);              // 1
    k_pack_x<<<Nn*Hh, 256>>>(x0);               // 2
    k_conv_int<1><<<296, 256>>>(nullptr, 0);    // 3  persistent + work-stealing (r14 form)
    k_conv_bnd<1><<<Nn*16, 256>>>(nullptr, 0);  // 4  8 pixels/block (r14 form)
    k_pack2<<<Nn*Hh, 256>>>(g1, b1);            // 5  inline coef1
    k_conv_int<2><<<296, 256>>>(x0, 1);         // 6
    k_conv_bnd<2><<<Nn*16, 256>>>(x0, 1);       // 7
    k_final<<<NCHW/1024, 256>>>(out, reg0, x0, g2, b2, out_size);  // 8  inline coef2
}